// round 3
// baseline (speedup 1.0000x reference)
#include <cuda_runtime.h>
#include <cstdint>

// ---------------------------------------------------------------------------
// CustomOrientationLoss: Z[v] = sum_{(u,v) edge} (x[u]-x[v])*(s[u]-s[v])
// (symmetric per edge -> compute once, scatter to both endpoints),
// then cos = <y,Z>/(|y||Z|), loss = mean(1-|cos|), ang = mean(deg(acos cos)).
//
// Harness dtype canonicalization (established empirically):
//   int64 edge_index -> int32   (round-1 OOB crash proves 25.6MB buffer)
//   bool  mask       -> int32   (round-2 1.5e-3 subset-decorrelation signature)
// ---------------------------------------------------------------------------

#define NMAX 100000

// Scratch: Z padded to 4 floats per node for vectorized RED + vectorized load.
__device__ float4 g_Z[NMAX];
__device__ double g_acc[3];   // [0] sum(1-|cos|), [1] sum(ang_deg), [2] count

// ---------------------------------------------------------------------------
__global__ void zero_kernel(int n) {
    int i = blockIdx.x * blockDim.x + threadIdx.x;
    if (i < n) g_Z[i] = make_float4(0.f, 0.f, 0.f, 0.f);
    if (i == 0) { g_acc[0] = 0.0; g_acc[1] = 0.0; g_acc[2] = 0.0; }
}

// ---------------------------------------------------------------------------
__global__ void edge_kernel(const float* __restrict__ x,
                            const float* __restrict__ s,
                            const int* __restrict__ ei,
                            int E) {
    int e = blockIdx.x * blockDim.x + threadIdx.x;
    if (e >= E) return;

    int a = ei[e];
    int b = ei[e + E];

    float sa = __ldg(s + a);
    float sb = __ldg(s + b);
    float ds = sb - sa;

    int a3 = a * 3, b3 = b * 3;
    float cx = (__ldg(x + b3 + 0) - __ldg(x + a3 + 0)) * ds;
    float cy = (__ldg(x + b3 + 1) - __ldg(x + a3 + 1)) * ds;
    float cz = (__ldg(x + b3 + 2) - __ldg(x + a3 + 2)) * ds;

    // Symmetric contribution: same vector added to both endpoints.
    float* pa = reinterpret_cast<float*>(&g_Z[a]);
    float* pb = reinterpret_cast<float*>(&g_Z[b]);
    asm volatile("red.global.add.v4.f32 [%0], {%1, %2, %3, %4};"
                 :: "l"(pa), "f"(cx), "f"(cy), "f"(cz), "f"(0.0f) : "memory");
    asm volatile("red.global.add.v4.f32 [%0], {%1, %2, %3, %4};"
                 :: "l"(pb), "f"(cx), "f"(cy), "f"(cz), "f"(0.0f) : "memory");
}

// ---------------------------------------------------------------------------
__global__ void node_kernel(const float* __restrict__ y,
                            const int* __restrict__ mask,   // bool -> int32
                            int N) {
    int i = blockIdx.x * blockDim.x + threadIdx.x;

    float l = 0.f, ang = 0.f, c = 0.f;
    if (i < N && mask[i] != 0) {
        float4 Z = g_Z[i];
        float y0 = y[3 * i], y1 = y[3 * i + 1], y2 = y[3 * i + 2];
        float dot = y0 * Z.x + y1 * Z.y + y2 * Z.z;
        float nz = sqrtf(Z.x * Z.x + Z.y * Z.y + Z.z * Z.z);
        float ny = sqrtf(y0 * y0 + y1 * y1 + y2 * y2);
        float cosv = dot / (ny * nz);
        l = 1.0f - fabsf(cosv);
        float cc = fminf(1.0f, fmaxf(-1.0f, cosv));
        ang = acosf(cc) * 57.295779513082320877f;  // degrees
        c = 1.0f;
    }

    // warp reduce
    #pragma unroll
    for (int o = 16; o > 0; o >>= 1) {
        l   += __shfl_down_sync(0xffffffffu, l,   o);
        ang += __shfl_down_sync(0xffffffffu, ang, o);
        c   += __shfl_down_sync(0xffffffffu, c,   o);
    }

    __shared__ float sl[8], sa_[8], sc[8];
    int wid = threadIdx.x >> 5;
    int lid = threadIdx.x & 31;
    if (lid == 0) { sl[wid] = l; sa_[wid] = ang; sc[wid] = c; }
    __syncthreads();

    if (threadIdx.x == 0) {
        float bl = 0.f, ba = 0.f, bc = 0.f;
        int nwarp = (blockDim.x + 31) >> 5;
        for (int w = 0; w < nwarp; w++) { bl += sl[w]; ba += sa_[w]; bc += sc[w]; }
        atomicAdd(&g_acc[0], (double)bl);
        atomicAdd(&g_acc[1], (double)ba);
        atomicAdd(&g_acc[2], (double)bc);
    }
}

// ---------------------------------------------------------------------------
__global__ void finalize_kernel(float* __restrict__ out) {
    double cnt = g_acc[2];
    if (cnt < 1.0) cnt = 1.0;
    out[0] = (float)(g_acc[0] / cnt);
    out[1] = (float)(g_acc[1] / cnt);
}

// ---------------------------------------------------------------------------
extern "C" void kernel_launch(void* const* d_in, const int* in_sizes, int n_in,
                              void* d_out, int out_size) {
    const float* x    = (const float*)d_in[0];   // [N,3]
    const float* y    = (const float*)d_in[1];   // [N,3]
    const float* s    = (const float*)d_in[2];   // [N]
    const int*   ei   = (const int*)d_in[3];     // [2,E] int32 (canonicalized)
    const int*   mask = (const int*)d_in[4];     // [N]   int32 (canonicalized bool)
    float* out = (float*)d_out;

    int N = in_sizes[2];
    int E = in_sizes[3] / 2;

    const int TB = 256;
    zero_kernel<<<(N + TB - 1) / TB, TB>>>(N);
    edge_kernel<<<(E + TB - 1) / TB, TB>>>(x, s, ei, E);
    node_kernel<<<(N + TB - 1) / TB, TB>>>(y, mask, N);
    finalize_kernel<<<1, 1>>>(out);
}

// round 4
// speedup vs baseline: 1.4526x; 1.4526x over previous
#include <cuda_runtime.h>
#include <cstdint>

// ---------------------------------------------------------------------------
// CustomOrientationLoss:
//   Z[v] = sum_{(u,v) edge} (x[u]-x[v])*(s[u]-s[v])   (symmetric per edge)
//   cos  = <y,Z>/(|y||Z|);  loss = mean(1-|cos|);  ang = mean(deg(acos cos))
//
// R4: pack (x,s) into aligned float4 table -> 2 gather sectors/edge (was ~4.75);
//     4 edges/thread (int4 index loads, 8-deep gather MLP);
//     fused zero+pack and node+finalize (last-block pattern): 3 launches.
// ---------------------------------------------------------------------------

#define NMAX 100000

__device__ float4 g_P[NMAX];            // (x0, x1, x2, s) packed, 16B aligned
__device__ float4 g_Z[NMAX];            // accumulator (w unused)
__device__ double g_acc[3];             // sum(1-|cos|), sum(ang_deg), count
__device__ unsigned int g_done;         // last-block-done counter

// ---------------------------------------------------------------------------
// Pack x+s into float4, zero Z, reset accumulators. One pass over N.
__global__ void pack_kernel(const float* __restrict__ x,
                            const float* __restrict__ s,
                            int N) {
    int i = blockIdx.x * blockDim.x + threadIdx.x;
    if (i < N) {
        g_P[i] = make_float4(x[3 * i], x[3 * i + 1], x[3 * i + 2], s[i]);
        g_Z[i] = make_float4(0.f, 0.f, 0.f, 0.f);
    }
    if (i == 0) {
        g_acc[0] = 0.0; g_acc[1] = 0.0; g_acc[2] = 0.0;
        g_done = 0u;
    }
}

// ---------------------------------------------------------------------------
// 4 edges per thread. Per edge: 2 aligned float4 gathers + 2 v4 REDs.
__global__ void edge_kernel(const int* __restrict__ ei, int E) {
    int t = blockIdx.x * blockDim.x + threadIdx.x;
    int e0 = t * 4;
    if (e0 >= E) return;

    if (e0 + 4 <= E) {
        int4 av = *reinterpret_cast<const int4*>(ei + e0);
        int4 bv = *reinterpret_cast<const int4*>(ei + E + e0);
        int as[4] = {av.x, av.y, av.z, av.w};
        int bs[4] = {bv.x, bv.y, bv.z, bv.w};

        // Batch all gathers first for MLP.
        float4 Pa[4], Pb[4];
        #pragma unroll
        for (int k = 0; k < 4; k++) {
            Pa[k] = __ldg(&g_P[as[k]]);
            Pb[k] = __ldg(&g_P[bs[k]]);
        }

        #pragma unroll
        for (int k = 0; k < 4; k++) {
            float ds = Pb[k].w - Pa[k].w;
            float cx = (Pb[k].x - Pa[k].x) * ds;
            float cy = (Pb[k].y - Pa[k].y) * ds;
            float cz = (Pb[k].z - Pa[k].z) * ds;
            float* pa = reinterpret_cast<float*>(&g_Z[as[k]]);
            float* pb = reinterpret_cast<float*>(&g_Z[bs[k]]);
            asm volatile("red.global.add.v4.f32 [%0], {%1, %2, %3, %4};"
                         :: "l"(pa), "f"(cx), "f"(cy), "f"(cz), "f"(0.0f) : "memory");
            asm volatile("red.global.add.v4.f32 [%0], {%1, %2, %3, %4};"
                         :: "l"(pb), "f"(cx), "f"(cy), "f"(cz), "f"(0.0f) : "memory");
        }
    } else {
        for (int e = e0; e < E; e++) {
            int a = ei[e], b = ei[E + e];
            float4 Pa = __ldg(&g_P[a]);
            float4 Pb = __ldg(&g_P[b]);
            float ds = Pb.w - Pa.w;
            float cx = (Pb.x - Pa.x) * ds;
            float cy = (Pb.y - Pa.y) * ds;
            float cz = (Pb.z - Pa.z) * ds;
            float* pa = reinterpret_cast<float*>(&g_Z[a]);
            float* pb = reinterpret_cast<float*>(&g_Z[b]);
            asm volatile("red.global.add.v4.f32 [%0], {%1, %2, %3, %4};"
                         :: "l"(pa), "f"(cx), "f"(cy), "f"(cz), "f"(0.0f) : "memory");
            asm volatile("red.global.add.v4.f32 [%0], {%1, %2, %3, %4};"
                         :: "l"(pb), "f"(cx), "f"(cy), "f"(cz), "f"(0.0f) : "memory");
        }
    }
}

// ---------------------------------------------------------------------------
// Node reduction + fused finalize (last block writes outputs).
__global__ void node_kernel(const float* __restrict__ y,
                            const int* __restrict__ mask,
                            int N, float* __restrict__ out) {
    int i = blockIdx.x * blockDim.x + threadIdx.x;

    float l = 0.f, ang = 0.f, c = 0.f;
    if (i < N && mask[i] != 0) {
        float4 Z = g_Z[i];
        float y0 = y[3 * i], y1 = y[3 * i + 1], y2 = y[3 * i + 2];
        float dot = y0 * Z.x + y1 * Z.y + y2 * Z.z;
        float nz = sqrtf(Z.x * Z.x + Z.y * Z.y + Z.z * Z.z);
        float ny = sqrtf(y0 * y0 + y1 * y1 + y2 * y2);
        float cosv = dot / (ny * nz);
        l = 1.0f - fabsf(cosv);
        float cc = fminf(1.0f, fmaxf(-1.0f, cosv));
        ang = acosf(cc) * 57.295779513082320877f;  // degrees
        c = 1.0f;
    }

    #pragma unroll
    for (int o = 16; o > 0; o >>= 1) {
        l   += __shfl_down_sync(0xffffffffu, l,   o);
        ang += __shfl_down_sync(0xffffffffu, ang, o);
        c   += __shfl_down_sync(0xffffffffu, c,   o);
    }

    __shared__ float sl[8], sa_[8], sc[8];
    int wid = threadIdx.x >> 5;
    int lid = threadIdx.x & 31;
    if (lid == 0) { sl[wid] = l; sa_[wid] = ang; sc[wid] = c; }
    __syncthreads();

    __shared__ bool is_last;
    if (threadIdx.x == 0) {
        float bl = 0.f, ba = 0.f, bc = 0.f;
        int nwarp = (blockDim.x + 31) >> 5;
        for (int w = 0; w < nwarp; w++) { bl += sl[w]; ba += sa_[w]; bc += sc[w]; }
        atomicAdd(&g_acc[0], (double)bl);
        atomicAdd(&g_acc[1], (double)ba);
        atomicAdd(&g_acc[2], (double)bc);
        __threadfence();
        unsigned int done = atomicAdd(&g_done, 1u);
        is_last = (done == gridDim.x - 1);
    }
    __syncthreads();

    if (is_last && threadIdx.x == 0) {
        double cnt = g_acc[2];
        if (cnt < 1.0) cnt = 1.0;
        out[0] = (float)(g_acc[0] / cnt);
        out[1] = (float)(g_acc[1] / cnt);
    }
}

// ---------------------------------------------------------------------------
extern "C" void kernel_launch(void* const* d_in, const int* in_sizes, int n_in,
                              void* d_out, int out_size) {
    const float* x    = (const float*)d_in[0];   // [N,3]
    const float* y    = (const float*)d_in[1];   // [N,3]
    const float* s    = (const float*)d_in[2];   // [N]
    const int*   ei   = (const int*)d_in[3];     // [2,E] int32
    const int*   mask = (const int*)d_in[4];     // [N]   int32 (bool)
    float* out = (float*)d_out;

    int N = in_sizes[2];
    int E = in_sizes[3] / 2;

    const int TB = 256;
    pack_kernel<<<(N + TB - 1) / TB, TB>>>(x, s, N);
    int nthreads = (E + 3) / 4;
    edge_kernel<<<(nthreads + TB - 1) / TB, TB>>>(ei, E);
    node_kernel<<<(N + TB - 1) / TB, TB>>>(y, mask, N, out);
}